// round 5
// baseline (speedup 1.0000x reference)
#include <cuda_runtime.h>
#include <cuda_pipeline.h>

// Fused preprocessing: rescale(1/255) -> bilinear 1280x960 -> 640x640
// (half-pixel centers) -> normalize -> NHWC->NCHW.
//
// Persistent double-buffered pipeline: 592 blocks (148 SMs x 4), each walks
// output rows u = bid, bid+592, ... While computing row-pair i from one smem
// buffer, cp.async streams row-pair i+1 (23 KB, contiguous: rows 2y,2y+1 are
// adjacent) into the other. DRAM read stream never idles.
//
// Per row: vertical scale is exactly 2.0 (frac 0.5 -> plain average, folded
// into normalize scale). Horizontal 1.5: px group {4t..4t+3} uses input cols
// {6t..6t+5}, fracs {.25,.75,.25,.75}. No clamping needed at these shapes.
// 160 threads: 1440 float4 cp.async / 160 = 9 per thread (stage),
// 160 px-groups / 160 = 1 per thread (compute) - perfectly balanced.

#define IN_H    1280
#define IN_W    960
#define OUT_HW  640
#define ROW_F   (IN_W * 3)          // 2880 floats per input row
#define PAIR_F4 (2 * ROW_F / 4)     // 1440 float4 per row-pair (23040 B)
#define NT      160
#define PLANE   (OUT_HW * OUT_HW)
#define NUNITS  (OUT_HW * 16)       // 10240 output rows total
#define NBLK    592                 // 148 SMs x 4 resident blocks

__global__ __launch_bounds__(NT) void preproc_kernel(
    const float* __restrict__ img,   // [16, 1280, 960, 3]
    const float* __restrict__ mean,  // [3]
    const float* __restrict__ stdv,  // [3]
    float* __restrict__ out)         // [16, 3, 640, 640]
{
    __shared__ float4 s_buf[2][PAIR_F4];   // 2 x 23040 B = 46080 B
    __shared__ float s_sc[3], s_bi[3];

    const int t = threadIdx.x;
    if (t < 3) {
        const float inv = 1.0f / stdv[t];
        s_sc[t] = (0.5f / 255.0f) * inv;   // vertical 0.5 folded in
        s_bi[t] = -mean[t] * inv;
    }
    const int bid = blockIdx.x;

    // ---- prologue: start copy of first row-pair into buffer 0 ----
    {
        const int u = bid;                       // bid < 592 <= NUNITS
        const int b = u / OUT_HW, y = u - b * OUT_HW;
        const float4* __restrict__ src =
            (const float4*)(img + (size_t)(b * IN_H + 2 * y) * ROW_F);
#pragma unroll
        for (int j = 0; j < 9; ++j)
            __pipeline_memcpy_async(&s_buf[0][t + j * NT], &src[t + j * NT], 16);
    }
    __pipeline_commit();

    int k = 0;
    for (int u = bid; u < NUNITS; u += NBLK, k ^= 1) {
        // ---- prefetch next row-pair into the other buffer ----
        const int un = u + NBLK;
        if (un < NUNITS) {
            const int bn = un / OUT_HW, yn = un - bn * OUT_HW;
            const float4* __restrict__ src =
                (const float4*)(img + (size_t)(bn * IN_H + 2 * yn) * ROW_F);
#pragma unroll
            for (int j = 0; j < 9; ++j)
                __pipeline_memcpy_async(&s_buf[k ^ 1][t + j * NT], &src[t + j * NT], 16);
        }
        __pipeline_commit();               // (empty group on last iter is fine)
        __pipeline_wait_prior(1);          // current pair's group complete
        __syncthreads();                   // visible to all threads

        // ---- compute row u from buffer k ----
        const int b = u / OUT_HW, y = u - b * OUT_HW;
        const float2* __restrict__ r0 = (const float2*)&s_buf[k][0] + 9 * t; // floats 18t
        const float2* __restrict__ r1 = r0 + ROW_F / 2;                      // +2880 floats

        float v[18];                       // row0+row1 sums, cols 6t..6t+5 x 3ch
#pragma unroll
        for (int j = 0; j < 9; ++j) {
            const float2 a = r0[j], c = r1[j];
            v[2 * j]     = a.x + c.x;
            v[2 * j + 1] = a.y + c.y;
        }

        const int ob = b * 3 * PLANE + y * OUT_HW + 4 * t;
#pragma unroll
        for (int c = 0; c < 3; ++c) {
            const float a0 = v[c],      a1 = v[3 + c],  a2 = v[6 + c];
            const float a3 = v[9 + c],  a4 = v[12 + c], a5 = v[15 + c];
            float4 o;
            o.x = fmaf(a1 - a0, 0.25f, a0);   // x = 4t   (fx=.25)
            o.y = fmaf(a2 - a1, 0.75f, a1);   // x = 4t+1 (fx=.75)
            o.z = fmaf(a4 - a3, 0.25f, a3);   // x = 4t+2
            o.w = fmaf(a5 - a4, 0.75f, a4);   // x = 4t+3
            const float sc = s_sc[c], bi = s_bi[c];
            o.x = fmaf(o.x, sc, bi);
            o.y = fmaf(o.y, sc, bi);
            o.z = fmaf(o.z, sc, bi);
            o.w = fmaf(o.w, sc, bi);
            __stcs((float4*)&out[ob + c * PLANE], o);
        }
        __syncthreads();   // all reads of s_buf[k] done before it is refilled
    }
}

extern "C" void kernel_launch(void* const* d_in, const int* in_sizes, int n_in,
                              void* d_out, int out_size) {
    const float* img  = (const float*)d_in[0];
    const float* mean = (const float*)d_in[1];
    const float* stdv = (const float*)d_in[2];
    float* out = (float*)d_out;

    preproc_kernel<<<NBLK, NT>>>(img, mean, stdv, out);
}

// round 6
// speedup vs baseline: 1.0374x; 1.0374x over previous
#include <cuda_runtime.h>
#include <cuda_pipeline.h>

// Fused preprocessing: rescale(1/255) -> bilinear 1280x960 -> 640x640
// (half-pixel centers) -> normalize -> NHWC->NCHW.
//
// Warp-autonomous version: each warp independently processes one
// (output row, 128-px segment) unit with NO block-wide barriers.
//   stage:  9 x cp.async.cg 16B per lane -> private 4.6KB smem slice
//           (cols [192s,192s+192) of input rows 2y and 2y+1, each 2304B
//           contiguous, 16B aligned).
//   sync:   __syncwarp only.
//   compute: lane = 4 output px from 18 contiguous smem floats per row;
//           vertical avg (exact 0.5) folded into normalize scale; coalesced
//           float4 __stcs per channel plane.
// Horizontal 1.5 scale: px group {4t..4t+3} uses cols {6t..6t+5}, fracs
// {.25,.75,.25,.75}; no clamping needed at these shapes. Scale/bias come
// from 3 lane-local divides + warp shuffles (no smem init barrier).

#define IN_H     1280
#define IN_W     960
#define OUT_HW   640
#define ROW_F    (IN_W * 3)        // 2880 floats per input row
#define SEG_PX   128               // output px per warp unit
#define SEG_F    576               // input floats per row per segment
#define SEG_F4   144               // float4 per row per segment
#define NSEG     5                 // 640 / 128
#define PLANE    (OUT_HW * OUT_HW)
#define WPB      8                 // warps per block
#define NT       (WPB * 32)
#define NUNITS   (OUT_HW * 16 * NSEG)   // 51200 warp units
#define NBLOCKS  (NUNITS / WPB)         // 6400

__global__ __launch_bounds__(NT) void preproc_kernel(
    const float* __restrict__ img,   // [16, 1280, 960, 3]
    const float* __restrict__ mean,  // [3]
    const float* __restrict__ stdv,  // [3]
    float* __restrict__ out)         // [16, 3, 640, 640]
{
    __shared__ float4 s_stage[WPB][2 * SEG_F4];   // 8 x 4608B = 36864B

    const int tid  = threadIdx.x;
    const int w    = tid >> 5;
    const int lane = tid & 31;
    const unsigned FULL = 0xFFFFFFFFu;

    // per-warp scale/bias (vertical 0.5 folded into scale)
    float sc_l = 0.0f, bi_l = 0.0f;
    if (lane < 3) {
        const float inv = 1.0f / __ldg(stdv + lane);
        sc_l = (0.5f / 255.0f) * inv;
        bi_l = -__ldg(mean + lane) * inv;
    }
    const float sc[3] = { __shfl_sync(FULL, sc_l, 0),
                          __shfl_sync(FULL, sc_l, 1),
                          __shfl_sync(FULL, sc_l, 2) };
    const float bi[3] = { __shfl_sync(FULL, bi_l, 0),
                          __shfl_sync(FULL, bi_l, 1),
                          __shfl_sync(FULL, bi_l, 2) };

    // unit -> (batch, row, segment); sequential units touch sequential memory
    const int u = blockIdx.x * WPB + w;          // 0..51199
    const int r = u / NSEG;                      // output row id 0..10239
    const int s = u - r * NSEG;                  // segment 0..4
    const int b = r / OUT_HW;                    // batch 0..15
    const int y = r - b * OUT_HW;                // row 0..639

    // ---- stage: 288 float4 (row0 seg ++ row1 seg) by 32 lanes, 9 each ----
    const float4* __restrict__ src0 =
        (const float4*)(img + (size_t)(b * IN_H + 2 * y) * ROW_F + s * SEG_F);
    const float4* __restrict__ src1 = src0 + ROW_F / 4;
    float4* dst = s_stage[w];
#pragma unroll
    for (int j = 0; j < 9; ++j) {
        const int idx = lane + 32 * j;
        const float4* src = (idx < SEG_F4) ? (src0 + idx) : (src1 + (idx - SEG_F4));
        __pipeline_memcpy_async(&dst[idx], src, 16);
    }
    __pipeline_commit();
    __pipeline_wait_prior(0);
    __syncwarp();

    // ---- compute: 4 px per lane from 18 contiguous floats per row ----
    const float2* __restrict__ p0 = (const float2*)dst + 9 * lane;        // row0
    const float2* __restrict__ p1 = p0 + SEG_F / 2;                       // row1

    float v[18];                     // row0+row1 sums (cols 6t..6t+5, 3 ch)
#pragma unroll
    for (int j = 0; j < 9; ++j) {
        const float2 a = p0[j], c = p1[j];
        v[2 * j]     = a.x + c.x;
        v[2 * j + 1] = a.y + c.y;
    }

    const int ob = b * 3 * PLANE + y * OUT_HW + s * SEG_PX + 4 * lane;
#pragma unroll
    for (int c = 0; c < 3; ++c) {
        const float a0 = v[c],      a1 = v[3 + c],  a2 = v[6 + c];
        const float a3 = v[9 + c],  a4 = v[12 + c], a5 = v[15 + c];
        float4 o;
        o.x = fmaf(a1 - a0, 0.25f, a0);   // fx = .25
        o.y = fmaf(a2 - a1, 0.75f, a1);   // fx = .75
        o.z = fmaf(a4 - a3, 0.25f, a3);
        o.w = fmaf(a5 - a4, 0.75f, a4);
        o.x = fmaf(o.x, sc[c], bi[c]);
        o.y = fmaf(o.y, sc[c], bi[c]);
        o.z = fmaf(o.z, sc[c], bi[c]);
        o.w = fmaf(o.w, sc[c], bi[c]);
        __stcs((float4*)&out[ob + c * PLANE], o);
    }
}

extern "C" void kernel_launch(void* const* d_in, const int* in_sizes, int n_in,
                              void* d_out, int out_size) {
    const float* img  = (const float*)d_in[0];
    const float* mean = (const float*)d_in[1];
    const float* stdv = (const float*)d_in[2];
    float* out = (float*)d_out;

    preproc_kernel<<<NBLOCKS, NT>>>(img, mean, stdv, out);
}